// round 7
// baseline (speedup 1.0000x reference)
#include <cuda_runtime.h>
#include <cuda_bf16.h>
#include <stdint.h>
#include <math.h>

#define NT 1024      // tokens
#define WD 300
#define PD 25
#define DIN 325      // WD+PD
#define HID 125
#define G4 500       // 4*HID
#define PRE_LD 1000  // pre layout: [t][dir*500 + oo]
#define TWOH 250
#define FC 100
#define NN (NT*NT)

// ---------------- scratch (no allocations allowed) ----------------
__device__ float g_x[NT * DIN];
__device__ float g_pre[NT * PRE_LD];
__device__ float g_h0[NT * TWOH];
__device__ float g_h1[NT * TWOH];
__device__ float g_A[NT * FC];
__device__ float g_B[NT * FC];
__device__ float g_scores_scratch[NN];
__device__ float g_colloss[NT];

// ---------------- helpers ----------------
__device__ __forceinline__ unsigned smem_u32(const void* p) {
    unsigned a;
    asm("{ .reg .u64 t; cvta.to.shared.u64 t, %1; cvt.u32.u64 %0, t; }"
        : "=r"(a) : "l"(p));
    return a;
}
__device__ __forceinline__ unsigned mapa_u32(unsigned a, unsigned r) {
    unsigned o;
    asm("mapa.shared::cluster.u32 %0, %1, %2;" : "=r"(o) : "r"(a), "r"(r));
    return o;
}
__device__ __forceinline__ float fast_sigmoid(float x) {
    return 1.f / (1.f + __expf(-x));
}
__device__ __forceinline__ float fast_tanh(float z) {
    z = fminf(fmaxf(z, -15.f), 15.f);
    float e = __expf(2.f * z);
    return __fdividef(e - 1.f, e + 1.f);
}
__device__ __forceinline__ void mbar_wait_acq_cluster(unsigned bar, unsigned parity) {
    unsigned done;
    asm volatile(
        "{ .reg .pred p;\n"
        "  mbarrier.try_wait.parity.acquire.cluster.shared::cta.b64 p, [%1], %2;\n"
        "  selp.b32 %0, 1, 0, p; }"
        : "=r"(done) : "r"(bar), "r"(parity) : "memory");
    while (!done) {
        asm volatile(
            "{ .reg .pred p;\n"
            "  mbarrier.try_wait.parity.acquire.cluster.shared::cta.b64 p, [%1], %2;\n"
            "  selp.b32 %0, 1, 0, p; }"
            : "=r"(done) : "r"(bar), "r"(parity) : "memory");
    }
}

// ---------------- embedding concat ----------------
__global__ void embed_kernel(const float* __restrict__ wv,
                             const int* __restrict__ pidx,
                             const float* __restrict__ pemb) {
    int t = blockIdx.x;
    int tid = threadIdx.x;
    if (tid < WD) {
        g_x[t * DIN + tid] = wv[t * WD + tid];
    } else if (tid < DIN) {
        g_x[t * DIN + tid] = pemb[pidx[t] * PD + (tid - WD)];
    }
}

// ---------------- 64x64-tile GEMM: C[m][n] = bias[n] + sum_k A[m,k]*B[n,k] ----------------
__global__ __launch_bounds__(256) void gemm64(
        const float* __restrict__ A, int lda,
        const float* __restrict__ B, int ldb,
        const float* __restrict__ bias,
        float* __restrict__ C, int ldc,
        int M, int N, int K) {
    __shared__ float As[16][64];
    __shared__ float Bs[16][64];
    int tid = threadIdx.x;
    int bm = blockIdx.y * 64, bn = blockIdx.x * 64;
    int lm = tid & 63, lk4 = (tid >> 6) * 4;
    int tr = tid >> 4, tc = tid & 15;
    float acc[4][4] = {};
    for (int k0 = 0; k0 < K; k0 += 16) {
        #pragma unroll
        for (int c = 0; c < 4; c++) {
            int k = k0 + lk4 + c;
            int m = bm + lm;
            As[lk4 + c][lm] = (m < M && k < K) ? A[(size_t)m * lda + k] : 0.f;
            int n = bn + lm;
            Bs[lk4 + c][lm] = (n < N && k < K) ? B[(size_t)n * ldb + k] : 0.f;
        }
        __syncthreads();
        #pragma unroll
        for (int kk = 0; kk < 16; kk++) {
            float4 a = *(const float4*)&As[kk][tr * 4];
            float4 b = *(const float4*)&Bs[kk][tc * 4];
            acc[0][0] = fmaf(a.x, b.x, acc[0][0]); acc[0][1] = fmaf(a.x, b.y, acc[0][1]);
            acc[0][2] = fmaf(a.x, b.z, acc[0][2]); acc[0][3] = fmaf(a.x, b.w, acc[0][3]);
            acc[1][0] = fmaf(a.y, b.x, acc[1][0]); acc[1][1] = fmaf(a.y, b.y, acc[1][1]);
            acc[1][2] = fmaf(a.y, b.z, acc[1][2]); acc[1][3] = fmaf(a.y, b.w, acc[1][3]);
            acc[2][0] = fmaf(a.z, b.x, acc[2][0]); acc[2][1] = fmaf(a.z, b.y, acc[2][1]);
            acc[2][2] = fmaf(a.z, b.z, acc[2][2]); acc[2][3] = fmaf(a.z, b.w, acc[2][3]);
            acc[3][0] = fmaf(a.w, b.x, acc[3][0]); acc[3][1] = fmaf(a.w, b.y, acc[3][1]);
            acc[3][2] = fmaf(a.w, b.z, acc[3][2]); acc[3][3] = fmaf(a.w, b.w, acc[3][3]);
        }
        __syncthreads();
    }
    #pragma unroll
    for (int i = 0; i < 4; i++) {
        int m = bm + tr * 4 + i;
        if (m >= M) break;
        #pragma unroll
        for (int j = 0; j < 4; j++) {
            int n = bn + tc * 4 + j;
            if (n < N) C[(size_t)m * ldc + n] = acc[i][j] + (bias ? bias[n] : 0.f);
        }
    }
}

// ---------------- cluster LSTM: 2 CTAs per direction ----------------
// CTA rank r owns h-dims [r?64:0, r?125:64). Each thread = (output, K-half).
// All weights live in registers. h halves exchanged via DSMEM + mbarrier.
__global__ __launch_bounds__(512, 1) __cluster_dims__(2, 1, 1)
void lstm_cluster(const float* __restrict__ pre,
                  const float* __restrict__ Whh,
                  float* __restrict__ hout) {
    __shared__ __align__(16) float hbuf[2][128];
    __shared__ float psum[256];
    __shared__ float actsm[256];
    __shared__ __align__(8) unsigned long long mbar;

    int dir = blockIdx.x >> 1;
    unsigned rank;
    asm("mov.u32 %0, %%cluster_ctarank;" : "=r"(rank));
    int tid = threadIdx.x;
    int w = tid >> 5, lane = tid & 31;
    int khalf = w >> 3;                       // 0: K [0,64)  1: K [64,128)
    bool is_local = (khalf == (int)rank);     // local warps' K-range = own dims
    int o_local = ((w & 7) << 5) | lane;      // 0..255
    int dim0 = rank ? 64 : 0;
    int ndim = rank ? 61 : 64;
    int peer_ndim = rank ? 64 : 61;
    int nout = ndim * 4;
    bool valid_o = o_local < nout;
    int gate = o_local & 3;                   // 0=i 1=f 2=g(tanh) 3=o
    int d = dim0 + (o_local >> 2);
    int oo = gate * HID + d;                  // 0..499
    int kbase = khalf << 6;

    // weights into registers (64 K-values, zero-padded past HID)
    const float* Wrow = Whh + (size_t)dir * G4 * HID + (size_t)oo * HID;
    float4 wr[16];
    #pragma unroll
    for (int q = 0; q < 16; q++) {
        float4 v = make_float4(0.f, 0.f, 0.f, 0.f);
        if (valid_o) {
            int k = kbase + 4 * q;
            v.x = (k     < HID) ? Wrow[k]     : 0.f;
            v.y = (k + 1 < HID) ? Wrow[k + 1] : 0.f;
            v.z = (k + 2 < HID) ? Wrow[k + 2] : 0.f;
            v.w = (k + 3 < HID) ? Wrow[k + 3] : 0.f;
        }
        wr[q] = v;
    }

    if (tid < 128) { hbuf[0][tid] = 0.f; hbuf[1][tid] = 0.f; }
    if (tid == 0) {
        asm volatile("mbarrier.init.shared.b64 [%0], %1;"
                     :: "r"(smem_u32(&mbar)), "r"(peer_ndim) : "memory");
        asm volatile("fence.mbarrier_init.release.cluster;" ::: "memory");
    }
    __syncthreads();
    asm volatile("barrier.cluster.arrive.aligned;" ::: "memory");
    asm volatile("barrier.cluster.wait.aligned;" ::: "memory");

    unsigned bar_local = smem_u32(&mbar);
    unsigned peer = rank ^ 1u;
    unsigned bar_remote = mapa_u32(bar_local, peer);
    unsigned hbuf_remote = mapa_u32(smem_u32(&hbuf[0][0]), peer);

    float c = 0.f;
    float pre_cur = 0.f;
    {
        int t0 = dir ? (NT - 1) : 0;
        if (is_local && valid_o)
            pre_cur = pre[(size_t)t0 * PRE_LD + dir * 500 + oo];
    }

    for (int s = 0; s < NT; s++) {
        int t = dir ? (NT - 1 - s) : s;
        int cur = s & 1, nxt = cur ^ 1;

        float pre_nxt = 0.f;
        if (is_local && valid_o && s + 1 < NT) {
            int tn = dir ? (t - 1) : (t + 1);
            pre_nxt = pre[(size_t)tn * PRE_LD + dir * 500 + oo];
        }

        // remote-half warps wait for peer's h (written at end of step s-1)
        if (!is_local && s > 0)
            mbar_wait_acq_cluster(bar_local, (unsigned)((s - 1) & 1));

        float a0 = 0.f, a1 = 0.f, a2 = 0.f, a3 = 0.f;
        const float4* h4 = (const float4*)&hbuf[cur][kbase];
        #pragma unroll
        for (int q = 0; q < 16; q++) {
            float4 hv = h4[q];
            a0 = fmaf(wr[q].x, hv.x, a0);
            a1 = fmaf(wr[q].y, hv.y, a1);
            a2 = fmaf(wr[q].z, hv.z, a2);
            a3 = fmaf(wr[q].w, hv.w, a3);
        }
        float part = (a0 + a1) + (a2 + a3);
        if (!is_local && valid_o) psum[o_local] = part;
        __syncthreads();

        if (is_local && valid_o) {
            float g = part + psum[o_local] + pre_cur;
            actsm[o_local] = (gate == 2) ? fast_tanh(g) : fast_sigmoid(g);
        }
        __syncthreads();

        if (tid < ndim) {
            int dd = dim0 + tid;
            float ig = actsm[tid * 4 + 0];
            float fg = actsm[tid * 4 + 1];
            float gg = actsm[tid * 4 + 2];
            float og = actsm[tid * 4 + 3];
            c = fmaf(fg, c, ig * gg);
            float h = og * fast_tanh(c);
            hbuf[nxt][dd] = h;
            hout[(size_t)t * TWOH + dir * HID + dd] = h;
            if (s + 1 < NT) {
                unsigned raddr = hbuf_remote + (unsigned)(nxt * 128 + dd) * 4u;
                asm volatile("st.shared::cluster.f32 [%0], %1;"
                             :: "r"(raddr), "f"(h) : "memory");
                asm volatile("mbarrier.arrive.release.cluster.shared::cluster.b64 _, [%0];"
                             :: "r"(bar_remote) : "memory");
            }
        }
        __syncthreads();
        pre_cur = pre_nxt;
    }

    asm volatile("barrier.cluster.arrive.aligned;" ::: "memory");
    asm volatile("barrier.cluster.wait.aligned;" ::: "memory");
}

// ---------------- pair scores ----------------
__global__ __launch_bounds__(256) void pair_kernel(
        const float* __restrict__ Ac,   // [NT][FC], fc1_b folded in
        const float* __restrict__ Bc,   // [NT][FC]
        const float* __restrict__ w2,   // [FC]
        const float* __restrict__ b2,   // [1]
        float* __restrict__ S) {
    __shared__ float Asm[32][101];
    __shared__ float Bsm[32][101];
    __shared__ float wsm[FC];
    int tx = threadIdx.x, ty = threadIdx.y;   // (32,8)
    int tid = ty * 32 + tx;
    int i0 = blockIdx.y * 32, j0 = blockIdx.x * 32;
    for (int idx = tid; idx < 32 * FC; idx += 256) {
        int r = idx / FC, f = idx - FC * r;
        Asm[r][f] = Ac[(i0 + r) * FC + f];
        Bsm[r][f] = Bc[(j0 + r) * FC + f];
    }
    if (tid < FC) wsm[tid] = w2[tid];
    __syncthreads();
    float fb = b2[0];
    float acc0 = 0.f, acc1 = 0.f, acc2 = 0.f, acc3 = 0.f;
    #pragma unroll 4
    for (int f = 0; f < FC; f++) {
        float b = Bsm[tx][f];
        float wv = wsm[f];
        acc0 = fmaf(fast_tanh(Asm[ty][f] + b), wv, acc0);
        acc1 = fmaf(fast_tanh(Asm[ty + 8][f] + b), wv, acc1);
        acc2 = fmaf(fast_tanh(Asm[ty + 16][f] + b), wv, acc2);
        acc3 = fmaf(fast_tanh(Asm[ty + 24][f] + b), wv, acc3);
    }
    int j = j0 + tx;
    float v[4] = {acc0 + fb, acc1 + fb, acc2 + fb, acc3 + fb};
    #pragma unroll
    for (int s = 0; s < 4; s++) {
        int i = i0 + ty + 8 * s;
        float out = (i == j || j == 0) ? 0.f : v[s];
        S[(size_t)i * NT + j] = out;
    }
}

// ---------------- per-column logsumexp + NLL ----------------
__global__ void colloss_kernel(const float* __restrict__ S,
                               const int* __restrict__ parents) {
    int tx = threadIdx.x, ty = threadIdx.y;  // (32,8)
    int j = blockIdx.x * 32 + tx;
    float m = -1e30f, ss = 0.f;
    for (int r = ty; r < NT; r += 8) {
        float x = S[(size_t)r * NT + j];
        if (x > m) { ss = ss * __expf(m - x) + 1.f; m = x; }
        else       { ss += __expf(x - m); }
    }
    __shared__ float Mv[8][33], Sv[8][33];
    Mv[ty][tx] = m; Sv[ty][tx] = ss;
    __syncthreads();
    if (ty == 0) {
        float M = Mv[0][tx], SS = Sv[0][tx];
        #pragma unroll
        for (int r = 1; r < 8; r++) {
            float m2 = Mv[r][tx], s2 = Sv[r][tx];
            if (m2 > M) { SS = SS * __expf(M - m2) + s2; M = m2; }
            else        { SS += s2 * __expf(m2 - M); }
        }
        int p = parents[j];
        g_colloss[j] = (M + logf(SS)) - S[(size_t)p * NT + j];
    }
}

__global__ void loss_kernel(float* __restrict__ lossptr) {
    __shared__ float sm[256];
    int tid = threadIdx.x;
    float s = 0.f;
    for (int i = tid; i < NT; i += 256) s += g_colloss[i];
    sm[tid] = s;
    __syncthreads();
    for (int off = 128; off > 0; off >>= 1) {
        if (tid < off) sm[tid] += sm[tid + off];
        __syncthreads();
    }
    if (tid == 0) *lossptr = sm[0] / (float)NT;
}

// ---------------- launch ----------------
extern "C" void kernel_launch(void* const* d_in, const int* in_sizes, int n_in,
                              void* d_out, int out_size) {
    (void)in_sizes; (void)n_in;
    const float* word_vecs = (const float*)d_in[0];
    const int*   pos_idx   = (const int*)d_in[1];
    const int*   parents   = (const int*)d_in[2];
    const float* pos_emb   = (const float*)d_in[3];
    const float* Wih0      = (const float*)d_in[4];
    const float* Whh0      = (const float*)d_in[5];
    const float* b0        = (const float*)d_in[6];
    const float* Wih1      = (const float*)d_in[7];
    const float* Whh1      = (const float*)d_in[8];
    const float* b1        = (const float*)d_in[9];
    const float* fc1_W     = (const float*)d_in[10];
    const float* fc1_b     = (const float*)d_in[11];
    const float* fc2_W     = (const float*)d_in[12];
    const float* fc2_b     = (const float*)d_in[13];
    float* out = (float*)d_out;

    float *px, *ppre, *ph0, *ph1, *pA, *pB, *pscratch;
    cudaGetSymbolAddress((void**)&px, g_x);
    cudaGetSymbolAddress((void**)&ppre, g_pre);
    cudaGetSymbolAddress((void**)&ph0, g_h0);
    cudaGetSymbolAddress((void**)&ph1, g_h1);
    cudaGetSymbolAddress((void**)&pA, g_A);
    cudaGetSymbolAddress((void**)&pB, g_B);
    cudaGetSymbolAddress((void**)&pscratch, g_scores_scratch);

    float* scores;
    float* lossp = nullptr;
    if (out_size >= NN) {
        scores = out + (out_size - NN);
        if (out_size > NN) lossp = out;
    } else {
        scores = pscratch;
        lossp = out;
    }

    // 1) embeddings
    embed_kernel<<<NT, 352>>>(word_vecs, pos_idx, pos_emb);

    // 2) pre(layer0) = x @ Wih0^T + b0  (both directions fused, N=1000)
    {
        dim3 g((PRE_LD + 63) / 64, (NT + 63) / 64);
        gemm64<<<g, 256>>>(px, DIN, Wih0, DIN, b0, ppre, PRE_LD, NT, PRE_LD, DIN);
    }
    // 3) layer0 recurrence: 2 clusters (fwd, bwd) x 2 CTAs
    lstm_cluster<<<4, 512>>>(ppre, Whh0, ph0);

    // 4) pre(layer1) = h0 @ Wih1^T + b1
    {
        dim3 g((PRE_LD + 63) / 64, (NT + 63) / 64);
        gemm64<<<g, 256>>>(ph0, TWOH, Wih1, TWOH, b1, ppre, PRE_LD, NT, PRE_LD, TWOH);
    }
    // 5) layer1 recurrence
    lstm_cluster<<<4, 512>>>(ppre, Whh1, ph1);

    // 6) A = h1 @ fc1_W[:, :250]^T + fc1_b ; B = h1 @ fc1_W[:, 250:]^T
    {
        dim3 g((FC + 63) / 64, (NT + 63) / 64);
        gemm64<<<g, 256>>>(ph1, TWOH, fc1_W, 2 * TWOH, fc1_b, pA, FC, NT, FC, TWOH);
        gemm64<<<g, 256>>>(ph1, TWOH, fc1_W + TWOH, 2 * TWOH, nullptr, pB, FC, NT, FC, TWOH);
    }

    // 7) pairwise scores (masked)
    {
        dim3 g(NT / 32, NT / 32), b(32, 8);
        pair_kernel<<<g, b>>>(pA, pB, fc2_W, fc2_b, scores);
    }

    // 8) loss
    if (lossp) {
        dim3 b(32, 8);
        colloss_kernel<<<NT / 32, b>>>(scores, parents);
        loss_kernel<<<1, 256>>>(lossp);
    }
}

// round 8
// speedup vs baseline: 1.6820x; 1.6820x over previous
#include <cuda_runtime.h>
#include <cuda_bf16.h>
#include <stdint.h>
#include <math.h>

#define NT 1024      // tokens
#define WD 300
#define PD 25
#define DIN 325      // WD+PD
#define HID 125
#define G4 500       // 4*HID
#define PRE_LD 1000  // pre layout: [t][dir*500 + oo]
#define TWOH 250
#define FC 100
#define NN (NT*NT)

// ---------------- scratch (no allocations allowed) ----------------
__device__ float g_x[NT * DIN];
__device__ float g_pre[NT * PRE_LD];
__device__ float g_h0[NT * TWOH];
__device__ float g_h1[NT * TWOH];
__device__ float g_A[NT * FC];
__device__ float g_B[NT * FC];
__device__ float g_scores_scratch[NN];
__device__ float g_colloss[NT];

// ---------------- helpers ----------------
__device__ __forceinline__ unsigned smem_u32(const void* p) {
    unsigned a;
    asm("{ .reg .u64 t; cvta.to.shared.u64 t, %1; cvt.u32.u64 %0, t; }"
        : "=r"(a) : "l"(p));
    return a;
}
__device__ __forceinline__ unsigned mapa_u32(unsigned a, unsigned r) {
    unsigned o;
    asm("mapa.shared::cluster.u32 %0, %1, %2;" : "=r"(o) : "r"(a), "r"(r));
    return o;
}
__device__ __forceinline__ float fast_sigmoid(float x) {
    return 1.f / (1.f + __expf(-x));
}
__device__ __forceinline__ float fast_tanh(float z) {
    z = fminf(fmaxf(z, -15.f), 15.f);
    float e = __expf(2.f * z);
    return __fdividef(e - 1.f, e + 1.f);
}
__device__ __forceinline__ void mbar_wait_acq_cluster(unsigned bar, unsigned parity) {
    unsigned done;
    asm volatile(
        "{ .reg .pred p;\n"
        "  mbarrier.try_wait.parity.acquire.cluster.shared::cta.b64 p, [%1], %2;\n"
        "  selp.b32 %0, 1, 0, p; }"
        : "=r"(done) : "r"(bar), "r"(parity) : "memory");
    while (!done) {
        asm volatile(
            "{ .reg .pred p;\n"
            "  mbarrier.try_wait.parity.acquire.cluster.shared::cta.b64 p, [%1], %2;\n"
            "  selp.b32 %0, 1, 0, p; }"
            : "=r"(done) : "r"(bar), "r"(parity) : "memory");
    }
}

// ---------------- embedding concat ----------------
__global__ void embed_kernel(const float* __restrict__ wv,
                             const int* __restrict__ pidx,
                             const float* __restrict__ pemb) {
    int t = blockIdx.x;
    int tid = threadIdx.x;
    if (tid < WD) {
        g_x[t * DIN + tid] = wv[t * WD + tid];
    } else if (tid < DIN) {
        g_x[t * DIN + tid] = pemb[pidx[t] * PD + (tid - WD)];
    }
}

// ---------------- 64x64-tile GEMM: C[m][n] = bias[n] + sum_k A[m,k]*B[n,k] ----------------
__global__ __launch_bounds__(256) void gemm64(
        const float* __restrict__ A, int lda,
        const float* __restrict__ B, int ldb,
        const float* __restrict__ bias,
        float* __restrict__ C, int ldc,
        int M, int N, int K) {
    __shared__ float As[16][64];
    __shared__ float Bs[16][64];
    int tid = threadIdx.x;
    int bm = blockIdx.y * 64, bn = blockIdx.x * 64;
    int lm = tid & 63, lk4 = (tid >> 6) * 4;
    int tr = tid >> 4, tc = tid & 15;
    float acc[4][4] = {};
    for (int k0 = 0; k0 < K; k0 += 16) {
        #pragma unroll
        for (int c = 0; c < 4; c++) {
            int k = k0 + lk4 + c;
            int m = bm + lm;
            As[lk4 + c][lm] = (m < M && k < K) ? A[(size_t)m * lda + k] : 0.f;
            int n = bn + lm;
            Bs[lk4 + c][lm] = (n < N && k < K) ? B[(size_t)n * ldb + k] : 0.f;
        }
        __syncthreads();
        #pragma unroll
        for (int kk = 0; kk < 16; kk++) {
            float4 a = *(const float4*)&As[kk][tr * 4];
            float4 b = *(const float4*)&Bs[kk][tc * 4];
            acc[0][0] = fmaf(a.x, b.x, acc[0][0]); acc[0][1] = fmaf(a.x, b.y, acc[0][1]);
            acc[0][2] = fmaf(a.x, b.z, acc[0][2]); acc[0][3] = fmaf(a.x, b.w, acc[0][3]);
            acc[1][0] = fmaf(a.y, b.x, acc[1][0]); acc[1][1] = fmaf(a.y, b.y, acc[1][1]);
            acc[1][2] = fmaf(a.y, b.z, acc[1][2]); acc[1][3] = fmaf(a.y, b.w, acc[1][3]);
            acc[2][0] = fmaf(a.z, b.x, acc[2][0]); acc[2][1] = fmaf(a.z, b.y, acc[2][1]);
            acc[2][2] = fmaf(a.z, b.z, acc[2][2]); acc[2][3] = fmaf(a.z, b.w, acc[2][3]);
            acc[3][0] = fmaf(a.w, b.x, acc[3][0]); acc[3][1] = fmaf(a.w, b.y, acc[3][1]);
            acc[3][2] = fmaf(a.w, b.z, acc[3][2]); acc[3][3] = fmaf(a.w, b.w, acc[3][3]);
        }
        __syncthreads();
    }
    #pragma unroll
    for (int i = 0; i < 4; i++) {
        int m = bm + tr * 4 + i;
        if (m >= M) break;
        #pragma unroll
        for (int j = 0; j < 4; j++) {
            int n = bn + tc * 4 + j;
            if (n < N) C[(size_t)m * ldc + n] = acc[i][j] + (bias ? bias[n] : 0.f);
        }
    }
}

// ---------------- cluster LSTM: 2 CTAs per direction, 256 thr/CTA ----------------
// CTA rank r owns h-dims [r*64, r*64+ndim). One thread per gate-output with the
// FULL K=128 (padded) weight row in registers. Matvec accumulates the LOCAL h
// half first, then waits on the peer's DSMEM-delivered half (latency hidden).
// Cell update via warp shuffles (gates of dim d are 4 consecutive lanes).
__global__ __launch_bounds__(256, 1) __cluster_dims__(2, 1, 1)
void lstm_cluster(const float* __restrict__ pre,
                  const float* __restrict__ Whh,
                  float* __restrict__ hout) {
    __shared__ __align__(16) float hbuf[2][128];
    __shared__ __align__(8) unsigned long long mbar;

    int dir = blockIdx.x >> 1;
    unsigned rank;
    asm("mov.u32 %0, %%cluster_ctarank;" : "=r"(rank));
    int tid = threadIdx.x;

    int dim0 = rank ? 64 : 0;
    int ndim = rank ? 61 : 64;
    int peer_ndim = rank ? 64 : 61;      // arrivals we expect from the peer
    int nout = ndim * 4;
    bool valid = tid < nout;
    int gate = tid & 3;                  // 0=i 1=f 2=g(tanh) 3=o
    int d = dim0 + (tid >> 2);
    int oo = gate * HID + d;             // 0..499

    int kloc = (int)rank * 64;           // local K half = own dims
    int krem = 64 - kloc;                // peer K half

    // full weight row in registers: local half then remote half (zero-padded)
    const float* Wrow = Whh + (size_t)dir * G4 * HID + (size_t)oo * HID;
    float4 wl[16], wm[16];
    #pragma unroll
    for (int q = 0; q < 16; q++) {
        float4 a = make_float4(0.f, 0.f, 0.f, 0.f);
        float4 b = make_float4(0.f, 0.f, 0.f, 0.f);
        if (valid) {
            int k = kloc + 4 * q;
            a.x = (k     < HID) ? Wrow[k]     : 0.f;
            a.y = (k + 1 < HID) ? Wrow[k + 1] : 0.f;
            a.z = (k + 2 < HID) ? Wrow[k + 2] : 0.f;
            a.w = (k + 3 < HID) ? Wrow[k + 3] : 0.f;
            int j = krem + 4 * q;
            b.x = (j     < HID) ? Wrow[j]     : 0.f;
            b.y = (j + 1 < HID) ? Wrow[j + 1] : 0.f;
            b.z = (j + 2 < HID) ? Wrow[j + 2] : 0.f;
            b.w = (j + 3 < HID) ? Wrow[j + 3] : 0.f;
        }
        wl[q] = a; wm[q] = b;
    }

    if (tid < 128) { hbuf[0][tid] = 0.f; hbuf[1][tid] = 0.f; }
    if (tid == 0) {
        asm volatile("mbarrier.init.shared.b64 [%0], %1;"
                     :: "r"(smem_u32(&mbar)), "r"(peer_ndim) : "memory");
        asm volatile("fence.mbarrier_init.release.cluster;" ::: "memory");
    }
    __syncthreads();
    asm volatile("barrier.cluster.arrive.aligned;" ::: "memory");
    asm volatile("barrier.cluster.wait.aligned;" ::: "memory");

    unsigned bar_local = smem_u32(&mbar);
    unsigned peer = rank ^ 1u;
    unsigned hbuf_remote = mapa_u32(smem_u32(&hbuf[0][0]), peer);
    unsigned bar_remote = mapa_u32(bar_local, peer);

    float c = 0.f;
    float pre_cur = 0.f;
    {
        int t0 = dir ? (NT - 1) : 0;
        if (valid) pre_cur = pre[(size_t)t0 * PRE_LD + dir * 500 + oo];
    }

    int qloc4 = kloc >> 2;   // float4 index of local half in hbuf
    int qrem4 = krem >> 2;

    for (int s = 0; s < NT; s++) {
        int t = dir ? (NT - 1 - s) : s;
        int cur = s & 1, nxt = cur ^ 1;

        float pre_nxt = 0.f;
        if (valid && s + 1 < NT) {
            int tn = dir ? (t - 1) : (t + 1);
            pre_nxt = pre[(size_t)tn * PRE_LD + dir * 500 + oo];
        }

        float a0 = 0.f, a1 = 0.f, a2 = 0.f, a3 = 0.f;
        const float4* h4 = (const float4*)&hbuf[cur][0];

        // local half first (hides peer DSMEM latency behind these FMAs)
        #pragma unroll
        for (int q = 0; q < 16; q++) {
            float4 hv = h4[qloc4 + q];
            a0 = fmaf(wl[q].x, hv.x, a0);
            a1 = fmaf(wl[q].y, hv.y, a1);
            a2 = fmaf(wl[q].z, hv.z, a2);
            a3 = fmaf(wl[q].w, hv.w, a3);
        }

        // peer half (h written at end of step s-1, flown in via DSMEM)
        if (s > 0) mbar_wait_acq_cluster(bar_local, (unsigned)((s - 1) & 1));
        #pragma unroll
        for (int q = 0; q < 16; q++) {
            float4 hv = h4[qrem4 + q];
            a0 = fmaf(wm[q].x, hv.x, a0);
            a1 = fmaf(wm[q].y, hv.y, a1);
            a2 = fmaf(wm[q].z, hv.z, a2);
            a3 = fmaf(wm[q].w, hv.w, a3);
        }

        float g = pre_cur + (a0 + a1) + (a2 + a3);
        float act = (gate == 2) ? fast_tanh(g) : fast_sigmoid(g);

        // gates of dim d live in lanes 4k..4k+3 of this warp
        float fg = __shfl_down_sync(0xFFFFFFFFu, act, 1);
        float gg = __shfl_down_sync(0xFFFFFFFFu, act, 2);
        float og = __shfl_down_sync(0xFFFFFFFFu, act, 3);
        if ((tid & 3) == 0) {
            c = fmaf(fg, c, act * gg);     // act = input gate on these lanes
            float h = og * fast_tanh(c);
            if (valid) {
                hbuf[nxt][d] = h;
                hout[(size_t)t * TWOH + dir * HID + d] = h;
                if (s + 1 < NT) {
                    unsigned raddr = hbuf_remote + (unsigned)(nxt * 128 + d) * 4u;
                    asm volatile("st.shared::cluster.f32 [%0], %1;"
                                 :: "r"(raddr), "f"(h) : "memory");
                    asm volatile("mbarrier.arrive.release.cluster.shared::cluster.b64 _, [%0];"
                                 :: "r"(bar_remote) : "memory");
                }
            }
        }
        __syncthreads();
        pre_cur = pre_nxt;
    }

    asm volatile("barrier.cluster.arrive.aligned;" ::: "memory");
    asm volatile("barrier.cluster.wait.aligned;" ::: "memory");
}

// ---------------- pair scores ----------------
__global__ __launch_bounds__(256) void pair_kernel(
        const float* __restrict__ Ac,   // [NT][FC], fc1_b folded in
        const float* __restrict__ Bc,   // [NT][FC]
        const float* __restrict__ w2,   // [FC]
        const float* __restrict__ b2,   // [1]
        float* __restrict__ S) {
    __shared__ float Asm[32][101];
    __shared__ float Bsm[32][101];
    __shared__ float wsm[FC];
    int tx = threadIdx.x, ty = threadIdx.y;   // (32,8)
    int tid = ty * 32 + tx;
    int i0 = blockIdx.y * 32, j0 = blockIdx.x * 32;
    for (int idx = tid; idx < 32 * FC; idx += 256) {
        int r = idx / FC, f = idx - FC * r;
        Asm[r][f] = Ac[(i0 + r) * FC + f];
        Bsm[r][f] = Bc[(j0 + r) * FC + f];
    }
    if (tid < FC) wsm[tid] = w2[tid];
    __syncthreads();
    float fb = b2[0];
    float acc0 = 0.f, acc1 = 0.f, acc2 = 0.f, acc3 = 0.f;
    #pragma unroll 4
    for (int f = 0; f < FC; f++) {
        float b = Bsm[tx][f];
        float wv = wsm[f];
        acc0 = fmaf(fast_tanh(Asm[ty][f] + b), wv, acc0);
        acc1 = fmaf(fast_tanh(Asm[ty + 8][f] + b), wv, acc1);
        acc2 = fmaf(fast_tanh(Asm[ty + 16][f] + b), wv, acc2);
        acc3 = fmaf(fast_tanh(Asm[ty + 24][f] + b), wv, acc3);
    }
    int j = j0 + tx;
    float v[4] = {acc0 + fb, acc1 + fb, acc2 + fb, acc3 + fb};
    #pragma unroll
    for (int s = 0; s < 4; s++) {
        int i = i0 + ty + 8 * s;
        float out = (i == j || j == 0) ? 0.f : v[s];
        S[(size_t)i * NT + j] = out;
    }
}

// ---------------- per-column logsumexp + NLL ----------------
__global__ void colloss_kernel(const float* __restrict__ S,
                               const int* __restrict__ parents) {
    int tx = threadIdx.x, ty = threadIdx.y;  // (32,8)
    int j = blockIdx.x * 32 + tx;
    float m = -1e30f, ss = 0.f;
    for (int r = ty; r < NT; r += 8) {
        float x = S[(size_t)r * NT + j];
        if (x > m) { ss = ss * __expf(m - x) + 1.f; m = x; }
        else       { ss += __expf(x - m); }
    }
    __shared__ float Mv[8][33], Sv[8][33];
    Mv[ty][tx] = m; Sv[ty][tx] = ss;
    __syncthreads();
    if (ty == 0) {
        float M = Mv[0][tx], SS = Sv[0][tx];
        #pragma unroll
        for (int r = 1; r < 8; r++) {
            float m2 = Mv[r][tx], s2 = Sv[r][tx];
            if (m2 > M) { SS = SS * __expf(M - m2) + s2; M = m2; }
            else        { SS += s2 * __expf(m2 - M); }
        }
        int p = parents[j];
        g_colloss[j] = (M + logf(SS)) - S[(size_t)p * NT + j];
    }
}

__global__ void loss_kernel(float* __restrict__ lossptr) {
    __shared__ float sm[256];
    int tid = threadIdx.x;
    float s = 0.f;
    for (int i = tid; i < NT; i += 256) s += g_colloss[i];
    sm[tid] = s;
    __syncthreads();
    for (int off = 128; off > 0; off >>= 1) {
        if (tid < off) sm[tid] += sm[tid + off];
        __syncthreads();
    }
    if (tid == 0) *lossptr = sm[0] / (float)NT;
}

// ---------------- launch ----------------
extern "C" void kernel_launch(void* const* d_in, const int* in_sizes, int n_in,
                              void* d_out, int out_size) {
    (void)in_sizes; (void)n_in;
    const float* word_vecs = (const float*)d_in[0];
    const int*   pos_idx   = (const int*)d_in[1];
    const int*   parents   = (const int*)d_in[2];
    const float* pos_emb   = (const float*)d_in[3];
    const float* Wih0      = (const float*)d_in[4];
    const float* Whh0      = (const float*)d_in[5];
    const float* b0        = (const float*)d_in[6];
    const float* Wih1      = (const float*)d_in[7];
    const float* Whh1      = (const float*)d_in[8];
    const float* b1        = (const float*)d_in[9];
    const float* fc1_W     = (const float*)d_in[10];
    const float* fc1_b     = (const float*)d_in[11];
    const float* fc2_W     = (const float*)d_in[12];
    const float* fc2_b     = (const float*)d_in[13];
    float* out = (float*)d_out;

    float *px, *ppre, *ph0, *ph1, *pA, *pB, *pscratch;
    cudaGetSymbolAddress((void**)&px, g_x);
    cudaGetSymbolAddress((void**)&ppre, g_pre);
    cudaGetSymbolAddress((void**)&ph0, g_h0);
    cudaGetSymbolAddress((void**)&ph1, g_h1);
    cudaGetSymbolAddress((void**)&pA, g_A);
    cudaGetSymbolAddress((void**)&pB, g_B);
    cudaGetSymbolAddress((void**)&pscratch, g_scores_scratch);

    float* scores;
    float* lossp = nullptr;
    if (out_size >= NN) {
        scores = out + (out_size - NN);
        if (out_size > NN) lossp = out;
    } else {
        scores = pscratch;
        lossp = out;
    }

    // 1) embeddings
    embed_kernel<<<NT, 352>>>(word_vecs, pos_idx, pos_emb);

    // 2) pre(layer0) = x @ Wih0^T + b0  (both directions fused, N=1000)
    {
        dim3 g((PRE_LD + 63) / 64, (NT + 63) / 64);
        gemm64<<<g, 256>>>(px, DIN, Wih0, DIN, b0, ppre, PRE_LD, NT, PRE_LD, DIN);
    }
    // 3) layer0 recurrence: 2 clusters (fwd, bwd) x 2 CTAs
    lstm_cluster<<<4, 256>>>(ppre, Whh0, ph0);

    // 4) pre(layer1) = h0 @ Wih1^T + b1
    {
        dim3 g((PRE_LD + 63) / 64, (NT + 63) / 64);
        gemm64<<<g, 256>>>(ph0, TWOH, Wih1, TWOH, b1, ppre, PRE_LD, NT, PRE_LD, TWOH);
    }
    // 5) layer1 recurrence
    lstm_cluster<<<4, 256>>>(ppre, Whh1, ph1);

    // 6) A = h1 @ fc1_W[:, :250]^T + fc1_b ; B = h1 @ fc1_W[:, 250:]^T
    {
        dim3 g((FC + 63) / 64, (NT + 63) / 64);
        gemm64<<<g, 256>>>(ph1, TWOH, fc1_W, 2 * TWOH, fc1_b, pA, FC, NT, FC, TWOH);
        gemm64<<<g, 256>>>(ph1, TWOH, fc1_W + TWOH, 2 * TWOH, nullptr, pB, FC, NT, FC, TWOH);
    }

    // 7) pairwise scores (masked)
    {
        dim3 g(NT / 32, NT / 32), b(32, 8);
        pair_kernel<<<g, b>>>(pA, pB, fc2_W, fc2_b, scores);
    }

    // 8) loss
    if (lossp) {
        dim3 b(32, 8);
        colloss_kernel<<<NT / 32, b>>>(scores, parents);
        loss_kernel<<<1, 256>>>(lossp);
    }
}